// round 3
// baseline (speedup 1.0000x reference)
#include <cuda_runtime.h>
#include <cstdint>

#define HH 128
#define WW 192
#define CC_TOT 256
#define BB 8
#define TILE_W 32
#define TILE_H 16
#define HALO_W 40
#define HALO_H 24
#define CHUNK 4
#define NCHUNK (CC_TOT / CHUNK)
#define NT 128
#define PLANE ((size_t)HH * WW)

// prev per-channel section: 24*40*4 = 3840 bytes data + 16-byte pad slot = 3856
#define PSEC 3856
#define PAD_REL 3840
#define PREV_BUF (CHUNK * PSEC)                       // 15424
#define CURR_BUF (CHUNK * TILE_H * TILE_W * 4)        // 8192
#define SM_PREV 0
#define SM_CURR (3 * PREV_BUF)                        // 46272
#define SM_SSP  (SM_CURR + 3 * CURR_BUF)              // 70848
#define SMEM_BYTES (SM_SSP + HALO_H * HALO_W * 4)     // 74688 -> 3 CTAs/SM

typedef unsigned long long u64;

__device__ __forceinline__ void F2(u64 &d, u64 a, u64 b) {
    asm("fma.rn.f32x2 %0, %1, %2, %0;" : "+l"(d) : "l"(a), "l"(b));
}
__device__ __forceinline__ u64 M2(u64 a, u64 b) {
    u64 d; asm("mul.rn.f32x2 %0, %1, %2;" : "=l"(d) : "l"(a), "l"(b)); return d;
}
__device__ __forceinline__ u64 PK(unsigned a, unsigned b) {
    u64 d; asm("mov.b64 %0, {%1, %2};" : "=l"(d) : "r"(a), "r"(b)); return d;
}
__device__ __forceinline__ unsigned LOW(u64 a) {
    unsigned l, h; asm("mov.b64 {%0, %1}, %2;" : "=r"(l), "=r"(h) : "l"(a)); return l;
}
__device__ __forceinline__ unsigned HIW(u64 a) {
    unsigned l, h; asm("mov.b64 {%0, %1}, %2;" : "=r"(l), "=r"(h) : "l"(a)); return h;
}
__device__ __forceinline__ void cp16(uint32_t dst, const void* src, int szbytes) {
    asm volatile("cp.async.cg.shared.global [%0], [%1], 16, %2;\n"
                 :: "r"(dst), "l"(src), "r"(szbytes) : "memory");
}

__global__ void __launch_bounds__(NT, 3)
corr_kernel(const float* __restrict__ curr, const float* __restrict__ prev,
            float* __restrict__ out)
{
    extern __shared__ char smem[];

    const int tid = threadIdx.x;
    const int g   = tid & 7;
    const int tx4 = g * 4;
    const int ty  = tid >> 3;
    const int x0  = blockIdx.x * TILE_W;
    const int y0  = blockIdx.y * TILE_H;
    const int bb  = blockIdx.z;

    const char* currB = (const char*)(curr + (size_t)bb * CC_TOT * PLANE);
    const char* prevB = (const char*)(prev + (size_t)bb * CC_TOT * PLANE);

    const uint32_t smA = (uint32_t)__cvta_generic_to_shared(smem);

    // ---- staging precompute ----
    // prev slot0 = tid, slot1 = tid+128 (tid<112) else pad slot; 240 f4 slots per cc
    const int sy0 = tid / 10,         sx0 = tid - sy0 * 10;
    const int sy1 = (tid + 128) / 10, sx1 = (tid + 128) - sy1 * 10;
    const int gy0 = y0 - 4 + sy0, gx0 = x0 - 4 + sx0 * 4;
    const int gy1 = y0 - 4 + sy1, gx1 = x0 - 4 + sx1 * 4;
    const bool ok0 = ((unsigned)gy0 < HH) && ((unsigned)gx0 < WW);
    const bool ok1 = ((unsigned)gy1 < HH) && ((unsigned)gx1 < WW) && (tid < 112);
    const int pixOff0 = ok0 ? (gy0 * WW + gx0) * 4 : 0;
    const int pixOff1 = ok1 ? (gy1 * WW + gx1) * 4 : 0;
    const int sz0 = ok0 ? 16 : 0;
    const int sz1 = ok1 ? 16 : 0;
    const uint32_t rel0 = (uint32_t)tid * 16;
    const uint32_t rel1 = (tid < 112) ? (uint32_t)(tid + 128) * 16 : (uint32_t)PAD_REL;
    const int cpixOff = ((y0 + ty) * WW + x0 + tx4) * 4;

    // ---- sq fallback slot (boundary rows + edge cols), dummy slot 0 for tid>=112 ----
    int s;
    if (tid < 40)       s = tid;                              // rows 0-3 (all quads)
    else if (tid < 80)  s = 200 + (tid - 40);                 // rows 20-23
    else if (tid < 112) { int i = tid - 80; s = (4 + (i >> 1)) * 10 + (i & 1) * 9; } // mid-row edges
    else                s = 0;                                // dummy
    const uint32_t sOff = (uint32_t)s * 16;

    // ---- accumulators ----
    u64 accL[33], accH[33];
    #pragma unroll
    for (int o = 0; o < 33; o++) { accL[o] = 0ull; accH[o] = 0ull; }
    u64 ssqL = 0ull, ssqH = 0ull;     // curr sum-of-squares
    u64 sqML = 0ull, sqMH = 0ull;     // prev sq, owned middle quad (row ty+4, cols 4g+4..)
    u64 sqFL = 0ull, sqFH = 0ull;     // prev sq, fallback slot

    // ---- staging helper ----
    auto issue = [&](const char* srcP, const char* srcC, uint32_t dP, uint32_t dC) {
        #pragma unroll
        for (int cc = 0; cc < CHUNK; cc++) {
            const size_t so = (size_t)cc * PLANE * 4;
            cp16(dP + cc * PSEC + rel0, srcP + so + pixOff0, sz0);
            cp16(dP + cc * PSEC + rel1, srcP + so + pixOff1, sz1);
            cp16(dC + cc * 2048 + rel0, srcC + so + cpixOff, 16);
        }
        asm volatile("cp.async.commit_group;\n" ::: "memory");
    };

    // preload chunks 0,1 -> bufs 0,1
    issue(prevB, currB, smA + SM_PREV, smA + SM_CURR);
    issue(prevB + (size_t)CHUNK * PLANE * 4, currB + (size_t)CHUNK * PLANE * 4,
          smA + SM_PREV + PREV_BUF, smA + SM_CURR + CURR_BUF);

    const char* srcPs = prevB + (size_t)2 * CHUNK * PLANE * 4;
    const char* srcCs = currB + (size_t)2 * CHUNK * PLANE * 4;
    int bC = 0, bS = 2;

    const int rowOff = (ty * HALO_W + tx4) * 4;
    const int cvOff  = (ty * TILE_W + tx4) * 4;

    #pragma unroll 1
    for (int k = 0; k < NCHUNK; k++) {
        if (k < NCHUNK - 1) asm volatile("cp.async.wait_group 1;\n" ::: "memory");
        else                asm volatile("cp.async.wait_group 0;\n" ::: "memory");
        __syncthreads();

        if (k < NCHUNK - 2) {
            issue(srcPs, srcCs, smA + SM_PREV + bS * PREV_BUF, smA + SM_CURR + bS * CURR_BUF);
            srcPs += (size_t)CHUNK * PLANE * 4;
            srcCs += (size_t)CHUNK * PLANE * 4;
            bS = (bS == 2) ? 0 : bS + 1;
        }

        const char* pbuf = smem + SM_PREV + bC * PREV_BUF;
        const char* cbuf = smem + SM_CURR + bC * CURR_BUF;

        #pragma unroll
        for (int cc = 0; cc < CHUNK; cc++) {
            // fallback prev-sq (1 LDS.128)
            {
                const ulonglong2 v = *(const ulonglong2*)(pbuf + cc * PSEC + sOff);
                F2(sqFL, v.x, v.x); F2(sqFH, v.y, v.y);
            }
            const ulonglong2 CV = *(const ulonglong2*)(cbuf + cc * 2048 + cvOff);
            const u64 cvL = CV.x, cvH = CV.y;
            F2(ssqL, cvL, cvL); F2(ssqH, cvH, cvH);

            const char* rowB = pbuf + cc * PSEC + rowOff;

#define ROW_FULL(R, O0) do { \
    const ulonglong2* _p = (const ulonglong2*)(rowB + (R) * (HALO_W * 4)); \
    const ulonglong2 q0 = _p[0], q1 = _p[1], q2 = _p[2]; \
    F2(accL[O0 + 0], cvL, q0.x); F2(accH[O0 + 0], cvH, q0.y); \
    F2(accL[O0 + 1], cvL, q0.y); F2(accH[O0 + 1], cvH, q1.x); \
    F2(accL[O0 + 2], cvL, q1.x); F2(accH[O0 + 2], cvH, q1.y); \
    F2(accL[O0 + 3], cvL, q1.y); F2(accH[O0 + 3], cvH, q2.x); \
    F2(accL[O0 + 4], cvL, q2.x); F2(accH[O0 + 4], cvH, q2.y); } while (0)

#define ROW_MID(R, M0) do { \
    const char* _rp = rowB + (R) * (HALO_W * 4); \
    const u64 a1 = *(const u64*)(_rp + 8); \
    const ulonglong2 q1 = *(const ulonglong2*)(_rp + 16); \
    const u64 a4 = *(const u64*)(_rp + 32); \
    const u64 P34 = PK(HIW(a1), LOW(q1.x)); \
    const u64 P56 = PK(HIW(q1.x), LOW(q1.y)); \
    const u64 P78 = PK(HIW(q1.y), LOW(a4)); \
    F2(accL[M0 + 0], cvL, P34);  F2(accH[M0 + 0], cvH, P56); \
    F2(accL[M0 + 1], cvL, q1.x); F2(accH[M0 + 1], cvH, q1.y); \
    F2(accL[M0 + 2], cvL, P56);  F2(accH[M0 + 2], cvH, P78); } while (0)

            ROW_FULL(0, 0);     // dy = -4
            ROW_FULL(2, 5);     // dy = -2
            ROW_MID (3, 10);    // dy = -1
            {                   // dy = 0: dx = -4,-2,-1,0,1,2,4 -> o13..o19; plus owned sq
                const ulonglong2* _p = (const ulonglong2*)(rowB + 4 * (HALO_W * 4));
                const ulonglong2 q0 = _p[0], q1 = _p[1], q2 = _p[2];
                F2(sqML, q1.x, q1.x); F2(sqMH, q1.y, q1.y);
                F2(accL[13], cvL, q0.x); F2(accH[13], cvH, q0.y);
                F2(accL[14], cvL, q0.y); F2(accH[14], cvH, q1.x);
                F2(accL[16], cvL, q1.x); F2(accH[16], cvH, q1.y);
                F2(accL[18], cvL, q1.y); F2(accH[18], cvH, q2.x);
                F2(accL[19], cvL, q2.x); F2(accH[19], cvH, q2.y);
                const u64 P34 = PK(HIW(q0.y), LOW(q1.x));
                const u64 P56 = PK(HIW(q1.x), LOW(q1.y));
                const u64 P78 = PK(HIW(q1.y), LOW(q2.x));
                F2(accL[15], cvL, P34); F2(accH[15], cvH, P56);
                F2(accL[17], cvL, P56); F2(accH[17], cvH, P78);
            }
            ROW_MID (5, 20);    // dy = 1
            ROW_FULL(6, 23);    // dy = 2
            ROW_FULL(8, 28);    // dy = 4
        }
        bC = (bC == 2) ? 0 : bC + 1;
    }

    // ---- epilogue: inverse norms into sspInv ----
    {
        float* ssp = (float*)(smem + SM_SSP);
        // owned middle quad: row ty+4, f4 col g+1
        {
            const float a = __uint_as_float(LOW(sqML)), b = __uint_as_float(HIW(sqML));
            const float c = __uint_as_float(LOW(sqMH)), d = __uint_as_float(HIW(sqMH));
            float4 r;
            r.x = a > 0.f ? rsqrtf(a) : 0.f;
            r.y = b > 0.f ? rsqrtf(b) : 0.f;
            r.z = c > 0.f ? rsqrtf(c) : 0.f;
            r.w = d > 0.f ? rsqrtf(d) : 0.f;
            ((float4*)ssp)[(ty + 4) * 10 + g + 1] = r;
        }
        if (tid < 112) {
            const float a = __uint_as_float(LOW(sqFL)), b = __uint_as_float(HIW(sqFL));
            const float c = __uint_as_float(LOW(sqFH)), d = __uint_as_float(HIW(sqFH));
            float4 r;
            r.x = a > 0.f ? rsqrtf(a) : 0.f;
            r.y = b > 0.f ? rsqrtf(b) : 0.f;
            r.z = c > 0.f ? rsqrtf(c) : 0.f;
            r.w = d > 0.f ? rsqrtf(d) : 0.f;
            ((float4*)ssp)[s] = r;
        }
    }
    __syncthreads();

    u64 invL, invH;
    {
        const float i0 = rsqrtf(__uint_as_float(LOW(ssqL)));
        const float i1 = rsqrtf(__uint_as_float(HIW(ssqL)));
        const float i2 = rsqrtf(__uint_as_float(LOW(ssqH)));
        const float i3 = rsqrtf(__uint_as_float(HIW(ssqH)));
        invL = PK(__float_as_uint(i0), __float_as_uint(i1));
        invH = PK(__float_as_uint(i2), __float_as_uint(i3));
    }

    const char* srow = smem + SM_SSP + rowOff;
    char* outPix = (char*)(out + ((size_t)bb * 33 * HH + (y0 + ty)) * WW + x0 + tx4);

#define EST(O, BL, BH) do { \
    ulonglong2 _r; \
    _r.x = M2(M2(accL[O], invL), (BL)); \
    _r.y = M2(M2(accH[O], invH), (BH)); \
    *(ulonglong2*)(outPix + (size_t)(O) * (PLANE * 4)) = _r; } while (0)

#define EROW_FULL(R, O0) do { \
    const ulonglong2* _p = (const ulonglong2*)(srow + (R) * (HALO_W * 4)); \
    const ulonglong2 q0 = _p[0], q1 = _p[1], q2 = _p[2]; \
    EST(O0 + 0, q0.x, q0.y); \
    EST(O0 + 1, q0.y, q1.x); \
    EST(O0 + 2, q1.x, q1.y); \
    EST(O0 + 3, q1.y, q2.x); \
    EST(O0 + 4, q2.x, q2.y); } while (0)

#define EROW_MID(R, M0) do { \
    const char* _rp = srow + (R) * (HALO_W * 4); \
    const u64 a1 = *(const u64*)(_rp + 8); \
    const ulonglong2 q1 = *(const ulonglong2*)(_rp + 16); \
    const u64 a4 = *(const u64*)(_rp + 32); \
    const u64 P34 = PK(HIW(a1), LOW(q1.x)); \
    const u64 P56 = PK(HIW(q1.x), LOW(q1.y)); \
    const u64 P78 = PK(HIW(q1.y), LOW(a4)); \
    EST(M0 + 0, P34, P56); \
    EST(M0 + 1, q1.x, q1.y); \
    EST(M0 + 2, P56, P78); } while (0)

    EROW_FULL(0, 0);
    EROW_FULL(2, 5);
    EROW_MID (3, 10);
    {
        const ulonglong2* _p = (const ulonglong2*)(srow + 4 * (HALO_W * 4));
        const ulonglong2 q0 = _p[0], q1 = _p[1], q2 = _p[2];
        EST(13, q0.x, q0.y);
        EST(14, q0.y, q1.x);
        EST(16, q1.x, q1.y);
        EST(18, q1.y, q2.x);
        EST(19, q2.x, q2.y);
        const u64 P34 = PK(HIW(q0.y), LOW(q1.x));
        const u64 P56 = PK(HIW(q1.x), LOW(q1.y));
        const u64 P78 = PK(HIW(q1.y), LOW(q2.x));
        EST(15, P34, P56);
        EST(17, P56, P78);
    }
    EROW_MID (5, 20);
    EROW_FULL(6, 23);
    EROW_FULL(8, 28);
}

extern "C" void kernel_launch(void* const* d_in, const int* in_sizes, int n_in,
                              void* d_out, int out_size)
{
    const float* curr = (const float*)d_in[0];
    const float* prev = (const float*)d_in[1];
    float* out = (float*)d_out;

    cudaFuncSetAttribute(corr_kernel, cudaFuncAttributeMaxDynamicSharedMemorySize, SMEM_BYTES);

    dim3 grid(WW / TILE_W, HH / TILE_H, BB);   // 6 x 8 x 8 = 384 blocks
    corr_kernel<<<grid, NT, SMEM_BYTES>>>(curr, prev, out);
}